// round 17
// baseline (speedup 1.0000x reference)
#include <cuda_runtime.h>
#include <cuda_bf16.h>
#include <math.h>

#define NROWS 65536
#define EDIM  1024
#define KST   4
#define DDIM  5
#define NBLK  304
#define WPB   8
#define NWARPS (NBLK * WPB)

typedef unsigned long long ull;

// 16-byte vector of two packed f32x2 operands
struct __align__(16) ull2v { ull x, y; };

// ---- device scratch (static globals; no allocation) ----
__device__ float  g_Y[(size_t)NROWS * 20];       // Wp projections of h0
__device__ float  g_WiT[20 * EDIM];              // d-major transposed Wi
__device__ float  g_biP[4 * EDIM];               // prefix sums of bi
__device__ double g_M[16 * 25];                  // M[i][j][d][d2] = Wp_i Wi_j
__device__ double g_c[16 * 5];                   // c[i][j][d] = Wp_i . bi_j
__device__ float  g_qc[5][4];                    // shift, half_l, off_b, halfw
__device__ float  g_row_norm[NROWS];

__constant__ int c_lo[5] = {0, 0, 0, 1, 2};
__constant__ int c_hi[5] = {7, 7, 7, 6, 6};

// ---- packed f32x2 helpers ----
__device__ __forceinline__ ull pk2(float lo, float hi) {
    ull r; asm("mov.b64 %0, {%1, %2};" : "=l"(r) : "f"(lo), "f"(hi)); return r;
}
__device__ __forceinline__ void upk2(ull v, float& a, float& b) {
    asm("mov.b64 {%0, %1}, %2;" : "=f"(a), "=f"(b) : "l"(v));
}
__device__ __forceinline__ ull ffma2_(ull a, ull b, ull c) {
    ull d; asm("fma.rn.f32x2 %0, %1, %2, %3;" : "=l"(d) : "l"(a), "l"(b), "l"(c));
    return d;
}
__device__ __forceinline__ float hsum2(ull v) {
    float x, y; upk2(v, x, y); return x + y;
}

// ============================================================
// Kernel 0: prep — small matrices, transposes, constants
// ============================================================
__global__ void qprep(const float* __restrict__ Wp,
                      const float* __restrict__ Wi,
                      const float* __restrict__ bi) {
    const int gt = blockIdx.x * 256 + threadIdx.x;
    const int NT = 8 * 256;

    if (gt < 5) {
        double lev = (gt < 3) ? 8.0 : ((gt == 3) ? 6.0 : 5.0);
        double half_l = (lev - 1.0) * (1.0 - 1e-3) / 2.0;
        double off_b  = (((int)lev) & 1) ? 0.0 : 0.5;
        g_qc[gt][0] = (float)tan(off_b / half_l);
        g_qc[gt][1] = (float)half_l;
        g_qc[gt][2] = (float)off_b;
        g_qc[gt][3] = (float)((int)lev / 2);
    }

    // Wi transpose: g_WiT[(i*5+d)*1024 + e] = Wi[(i*1024+e)*5 + d]
    for (int idx = gt; idx < 20 * EDIM; idx += NT) {
        int col = idx >> 10, e = idx & 1023;
        g_WiT[idx] = Wi[((size_t)(col / 5) * EDIM + e) * DDIM + (col % 5)];
    }

    // bias prefixes
    for (int e = gt; e < EDIM; e += NT) {
        float s = 0.f;
        #pragma unroll
        for (int j = 0; j < 4; j++) { s += bi[j * EDIM + e]; g_biP[j * EDIM + e] = s; }
    }

    // M and c in double
    for (int dot = gt; dot < 480; dot += NT) {
        if (dot < 400) {
            int ij = dot / 25, dd = dot % 25;
            int i = ij / 4, j = ij % 4, d = dd / 5, d2 = dd % 5;
            double s = 0.0;
            for (int e = 0; e < EDIM; e++)
                s += (double)Wp[(size_t)(i * 5 + d) * EDIM + e] *
                     (double)Wi[((size_t)j * EDIM + e) * DDIM + d2];
            g_M[ij * 25 + dd] = s;
        } else {
            int k = dot - 400; int ij = k / 5, d = k % 5;
            int i = ij / 4, j = ij % 4;
            double s = 0.0;
            for (int e = 0; e < EDIM; e++)
                s += (double)Wp[(size_t)(i * 5 + d) * EDIM + e] * (double)bi[j * EDIM + e];
            g_c[ij * 5 + d] = s;
        }
    }
}

// ============================================================
// Kernel 1: GEMM1 — Y[row][20] = Wp . h0  (warp-per-pair)
// ============================================================
__global__ __launch_bounds__(256, 2) void qg1(const float* __restrict__ h_in,
                                              const float* __restrict__ Wp) {
    const int t = threadIdx.x, lane = t & 31, warp = t >> 5;
    const int gwarp = blockIdx.x * WPB + warp;

    for (int rowA = 2 * gwarp; rowA < NROWS; rowA += 2 * NWARPS) {
        const int rowB = rowA + 1;
        const ull2v* hA = (const ull2v*)(h_in + (size_t)rowA * EDIM);
        const ull2v* hB = (const ull2v*)(h_in + (size_t)rowB * EDIM);
        ull rA[16], rB[16];
        #pragma unroll
        for (int jj = 0; jj < 8; jj++) {
            ull2v va = hA[jj * 32 + lane];
            ull2v vb = hB[jj * 32 + lane];
            rA[2*jj] = va.x; rA[2*jj+1] = va.y;
            rB[2*jj] = vb.x; rB[2*jj+1] = vb.y;
        }

        #pragma unroll
        for (int g = 0; g < 2; g++) {
            ull aA[10], aB[10];
            #pragma unroll
            for (int c = 0; c < 10; c++) { aA[c] = 0ull; aB[c] = 0ull; }
            #pragma unroll
            for (int c = 0; c < 10; c++) {
                const ull2v* wr = (const ull2v*)(Wp + (size_t)(g * 10 + c) * EDIM);
                #pragma unroll
                for (int jj = 0; jj < 8; jj++) {
                    ull2v w = wr[jj * 32 + lane];
                    aA[c] = ffma2_(w.x, rA[2*jj],   aA[c]);
                    aA[c] = ffma2_(w.y, rA[2*jj+1], aA[c]);
                    aB[c] = ffma2_(w.x, rB[2*jj],   aB[c]);
                    aB[c] = ffma2_(w.y, rB[2*jj+1], aB[c]);
                }
            }
            float vA = 0.f, vB = 0.f;
            #pragma unroll
            for (int c = 0; c < 10; c++) {
                float sA = hsum2(aA[c]);
                float sB = hsum2(aB[c]);
                #pragma unroll
                for (int off = 16; off; off >>= 1) {
                    sA += __shfl_xor_sync(0xffffffffu, sA, off);
                    sB += __shfl_xor_sync(0xffffffffu, sB, off);
                }
                if (lane == c) { vA = sA; vB = sB; }
            }
            if (lane < 10) {
                g_Y[(size_t)rowA * 20 + g * 10 + lane] = vA;
                g_Y[(size_t)rowB * 20 + g * 10 + lane] = vB;
            }
        }
    }
}

// ============================================================
// Kernel 2: middle — 5-dim recurrence + gumbel argmax, thread-per-row
// ============================================================
__global__ __launch_bounds__(256) void qmid(const float* __restrict__ bp,
                                            const float* __restrict__ temp,
                                            const float* __restrict__ u,
                                            float* __restrict__ out_code) {
    const int row = blockIdx.x * 256 + threadIdx.x;
    float te = temp[0];
    te = fmaxf(te * te, 1e-8f);
    const float inv_t2 = 1.0f / (te * te);

    float P[20];
    #pragma unroll
    for (int k = 0; k < 20; k++) P[k] = g_Y[(size_t)row * 20 + k];

    float zs[20];
    #pragma unroll
    for (int i = 0; i < KST; i++) {
        float h[5];
        #pragma unroll
        for (int d = 0; d < 5; d++) {
            double a = (double)P[i * 5 + d] + (double)__ldg(bp + i * 5 + d);
            #pragma unroll
            for (int j = 0; j < KST; j++) {
                if (j < i) {
                    const double* M = g_M + (i * 4 + j) * 25 + d * 5;
                    double s = g_c[(i * 4 + j) * 5 + d];
                    #pragma unroll
                    for (int d2 = 0; d2 < 5; d2++) s += M[d2] * (double)zs[j * 5 + d2];
                    a -= s;
                }
            }
            h[d] = (float)a;
        }
        #pragma unroll
        for (int d = 0; d < 5; d++) {
            float z = tanhf(h[d] + g_qc[d][0]) * g_qc[d][1] - g_qc[d][2];
            const float* ub = u + ((((size_t)i * NROWS + row) * DDIM + d) << 3);
            float4 u0 = __ldg((const float4*)ub);
            float4 u1 = __ldg((const float4*)ub + 1);
            float uu[8] = {u0.x, u0.y, u0.z, u0.w, u1.x, u1.y, u1.z, u1.w};
            const int lo = c_lo[d], hi = c_hi[d];
            float best = -INFINITY;
            int bc = lo;
            #pragma unroll
            for (int c = 0; c < 8; c++) {
                if (c >= lo && c <= hi) {
                    float g  = -logf(-logf(uu[c] + 1e-20f) + 1e-20f);
                    float df = z - (float)(c - 4);
                    float val = -(df * df) * inv_t2 + g;
                    if (val > best) { best = val; bc = c; }   // first-max tie-break
                }
            }
            float zq = (float)(bc - 4) / g_qc[d][3];
            zs[i * 5 + d] = zq;
            out_code[(size_t)row * 20 + i * 5 + d] = zq;
        }
    }
}

// ============================================================
// Kernel 3: GEMM2 — q = codes @ WiT + biasPrefix; loss capture per stage.
// Block handles 8 rows per iteration; thread t owns e = 4t..4t+3.
// ============================================================
__global__ __launch_bounds__(256, 2) void qg2(const float* __restrict__ h_in,
                                              const float* __restrict__ p,
                                              const float* __restrict__ code,
                                              float* __restrict__ out_q) {
    __shared__ ull   zsm[8][20];
    __shared__ int   ssel[8];
    __shared__ float spart[8][8];   // [warp][row]

    const int t = threadIdx.x, lane = t & 31, warp = t >> 5;
    const ull NEG1 = pk2(-1.0f, -1.0f);
    const ull ONE  = pk2(1.0f, 1.0f);

    for (int base = blockIdx.x * 8; base < NROWS; base += NBLK * 8) {
        if (t < 160) {
            float v = code[(size_t)(base + t / 20) * 20 + (t % 20)];
            zsm[t / 20][t % 20] = pk2(v, v);
        }
        if (t < 8) {
            float pr = p[base + t];
            int s = -1;
            #pragma unroll
            for (int i = 0; i < 4; i++)
                if (((float)i * 0.25f < pr) && (pr <= (float)(i + 1) * 0.25f)) s = i;
            ssel[t] = s;
        }
        __syncthreads();

        ull acc[8][2];
        float ssq[8];
        #pragma unroll
        for (int r = 0; r < 8; r++) { acc[r][0] = 0ull; acc[r][1] = 0ull; ssq[r] = 0.f; }

        // p selects nothing -> loss uses ||h0||^2
        #pragma unroll
        for (int r = 0; r < 8; r++) {
            if (ssel[r] == -1) {
                ull2v h0 = *(const ull2v*)(h_in + (size_t)(base + r) * EDIM + t * 4);
                ssq[r] = hsum2(ffma2_(h0.x, h0.x, ffma2_(h0.y, h0.y, 0ull)));
            }
        }

        #pragma unroll
        for (int i = 0; i < 4; i++) {
            const float* wb = g_WiT + (size_t)i * 5 * EDIM;
            ull2v w0 = *(const ull2v*)(wb + 0 * EDIM + t * 4);
            ull2v w1 = *(const ull2v*)(wb + 1 * EDIM + t * 4);
            ull2v w2 = *(const ull2v*)(wb + 2 * EDIM + t * 4);
            ull2v w3 = *(const ull2v*)(wb + 3 * EDIM + t * 4);
            ull2v w4 = *(const ull2v*)(wb + 4 * EDIM + t * 4);
            #pragma unroll
            for (int r = 0; r < 8; r++) {
                ull z0 = zsm[r][i * 5 + 0], z1 = zsm[r][i * 5 + 1], z2 = zsm[r][i * 5 + 2];
                ull z3 = zsm[r][i * 5 + 3], z4 = zsm[r][i * 5 + 4];
                ull ax = acc[r][0], ay = acc[r][1];
                ax = ffma2_(w0.x, z0, ax); ay = ffma2_(w0.y, z0, ay);
                ax = ffma2_(w1.x, z1, ax); ay = ffma2_(w1.y, z1, ay);
                ax = ffma2_(w2.x, z2, ax); ay = ffma2_(w2.y, z2, ay);
                ax = ffma2_(w3.x, z3, ax); ay = ffma2_(w3.y, z3, ay);
                ax = ffma2_(w4.x, z4, ax); ay = ffma2_(w4.y, z4, ay);
                acc[r][0] = ax; acc[r][1] = ay;
            }
            // loss capture at the selected stage
            #pragma unroll
            for (int r = 0; r < 8; r++) {
                if (ssel[r] == i) {
                    ull2v h0  = *(const ull2v*)(h_in + (size_t)(base + r) * EDIM + t * 4);
                    ull2v bpv = *(const ull2v*)(g_biP + (size_t)i * EDIM + t * 4);
                    ull dx = ffma2_(acc[r][0], NEG1, h0.x); dx = ffma2_(bpv.x, NEG1, dx);
                    ull dy = ffma2_(acc[r][1], NEG1, h0.y); dy = ffma2_(bpv.y, NEG1, dy);
                    ssq[r] = hsum2(ffma2_(dx, dx, ffma2_(dy, dy, 0ull)));
                }
            }
        }

        // final q = acc + biasPrefix[3]
        ull2v b3 = *(const ull2v*)(g_biP + (size_t)3 * EDIM + t * 4);
        #pragma unroll
        for (int r = 0; r < 8; r++) {
            ull2v q;
            q.x = ffma2_(b3.x, ONE, acc[r][0]);
            q.y = ffma2_(b3.y, ONE, acc[r][1]);
            __stcs((uint4*)(out_q + (size_t)(base + r) * EDIM + t * 4), *(const uint4*)&q);
        }

        // ssq block reduce -> row norms
        #pragma unroll
        for (int r = 0; r < 8; r++) {
            float s = ssq[r];
            #pragma unroll
            for (int off = 16; off; off >>= 1) s += __shfl_xor_sync(0xffffffffu, s, off);
            if (lane == 0) spart[warp][r] = s;
        }
        __syncthreads();
        if (t < 8) {
            float s = 0.f;
            #pragma unroll
            for (int w = 0; w < 8; w++) s += spart[w][t];
            g_row_norm[base + t] = sqrtf(s);
        }
        __syncthreads();
    }
}

// ---- deterministic mean of per-row norms ----
__global__ __launch_bounds__(1024) void qfinal(float* __restrict__ out_loss) {
    __shared__ float sh[1024];
    const float4* v = (const float4*)g_row_norm;
    float s = 0.f;
    for (int idx = threadIdx.x; idx < NROWS / 4; idx += 1024) {
        float4 a = v[idx];
        s += (a.x + a.y) + (a.z + a.w);
    }
    sh[threadIdx.x] = s;
    __syncthreads();
    for (int stride = 512; stride; stride >>= 1) {
        if (threadIdx.x < (unsigned)stride) sh[threadIdx.x] += sh[threadIdx.x + stride];
        __syncthreads();
    }
    if (threadIdx.x == 0) out_loss[0] = sh[0] / (float)NROWS;
}

extern "C" void kernel_launch(void* const* d_in, const int* in_sizes, int n_in,
                              void* d_out, int out_size) {
    const float* h_in = (const float*)d_in[0];
    const float* Wp   = (const float*)d_in[1];
    const float* bp   = (const float*)d_in[2];
    const float* Wi   = (const float*)d_in[3];
    const float* bi   = (const float*)d_in[4];
    const float* temp = (const float*)d_in[5];
    const float* u    = (const float*)d_in[6];
    const float* p    = (const float*)d_in[7];

    float* out      = (float*)d_out;
    float* out_q    = out;                                   // (N, E)
    float* out_code = out + (size_t)NROWS * EDIM;            // (N, K*D)
    float* out_loss = out_code + (size_t)NROWS * KST * DDIM; // scalar

    qprep<<<8, 256>>>(Wp, Wi, bi);
    qg1<<<NBLK, 256>>>(h_in, Wp);
    qmid<<<NROWS / 256, 256>>>(bp, temp, u, out_code);
    qg2<<<NBLK, 256>>>(h_in, p, out_code, out_q);
    qfinal<<<1, 1024>>>(out_loss);
}